// round 3
// baseline (speedup 1.0000x reference)
#include <cuda_runtime.h>
#include <cuda_bf16.h>
#include <math.h>

// Fixed shapes for HWnet_base_56667798503819
#define BQ 131072   // queries
#define TT 2048     // table size
#define DD 64       // feature dim
#define EE 4        // edge size
#define WW (2*EE+1) // window = 9

// 8 lanes per query; each lane owns 8 floats of D=64 (two float4).
#define LANES 8
#define BLOCK_THREADS 256
#define Q_PER_BLOCK (BLOCK_THREADS / LANES)   // 32

__global__ __launch_bounds__(BLOCK_THREADS)
void hwnet_kernel(const float* __restrict__ x,
                  const float* __restrict__ ev,
                  const float* __restrict__ tk,
                  const float* __restrict__ vec,
                  float* __restrict__ out)
{
    // Stage both scalar tables in shared memory: all per-query scalar reads
    // become broadcast/low-conflict LDS (1 wavefront) instead of multi-line
    // global loads (up to 4 wavefronts each).
    __shared__ float ev_s[TT];
    __shared__ float tk_s[TT];
    {
        const float4* ev4 = reinterpret_cast<const float4*>(ev);
        const float4* tk4 = reinterpret_cast<const float4*>(tk);
        float4* evs4 = reinterpret_cast<float4*>(ev_s);
        float4* tks4 = reinterpret_cast<float4*>(tk_s);
        #pragma unroll
        for (int i = threadIdx.x; i < TT / 4; i += BLOCK_THREADS) {
            evs4[i] = ev4[i];
            tks4[i] = tk4[i];
        }
    }
    __syncthreads();

    const int gtid = blockIdx.x * BLOCK_THREADS + threadIdx.x;
    const int q    = gtid >> 3;      // query index
    const int sub  = gtid & 7;       // 8-float slice within D=64

    const float xv = __ldg(&x[q]);

    // ---- nearest anchor: analytic guess + exact 5-candidate argmin fixup ----
    // Table is sorted and near-linear; the affine-inverse guess is within +-1
    // of the true argmin, so checking guess-2..guess+2 against the REAL table
    // values reproduces jnp.argmin exactly (ascending scan + strict '<' gives
    // first-min tie-break).
    const float e0 = ev_s[0];
    const float eN = ev_s[TT - 1];
    const float invstep = (float)(TT - 1) / (eN - e0);
    int g = __float2int_rn((xv - e0) * invstep);
    g = min(max(g, 0), TT - 1);

    int idx = -1;
    float best = INFINITY;
    #pragma unroll
    for (int k = 0; k < 5; ++k) {
        int i = min(max(g - 2 + k, 0), TT - 1);
        float d = fabsf(xv - ev_s[i]);
        if (d < best) { best = d; idx = i; }   // strict < => lowest index on ties
    }

    const float tcare = tk_s[idx];             // takecare at UNCLIPPED idx
    const int idx_c = min(max(idx, EE), TT - 1 - EE);
    const int base  = idx_c - EE;

    // ---- window logits + softmax (redundant across 8 lanes, uniform) ----
    float w[WW];
    float m = -INFINITY;
    #pragma unroll
    for (int j = 0; j < WW; ++j) {
        float d = xv - ev_s[base + j];
        w[j] = -(d * d) * tcare;
        m = fmaxf(m, w[j]);
    }
    float s = 0.f;
    #pragma unroll
    for (int j = 0; j < WW; ++j) {
        w[j] = __expf(w[j] - m);
        s += w[j];
    }
    const float inv = 1.0f / s;
    #pragma unroll
    for (int j = 0; j < WW; ++j) w[j] *= inv;  // fold normalization into weights

    // ---- gather 9 rows, 8 floats per lane (2 x float4, coalesced 256B/row) ----
    const float* vrow = vec + (size_t)base * DD + sub * 8;
    float4 a0 = make_float4(0.f, 0.f, 0.f, 0.f);
    float4 a1 = make_float4(0.f, 0.f, 0.f, 0.f);
    #pragma unroll
    for (int j = 0; j < WW; ++j) {
        const float4 v0 = *reinterpret_cast<const float4*>(vrow + (size_t)j * DD);
        const float4 v1 = *reinterpret_cast<const float4*>(vrow + (size_t)j * DD + 4);
        a0.x = fmaf(w[j], v0.x, a0.x);
        a0.y = fmaf(w[j], v0.y, a0.y);
        a0.z = fmaf(w[j], v0.z, a0.z);
        a0.w = fmaf(w[j], v0.w, a0.w);
        a1.x = fmaf(w[j], v1.x, a1.x);
        a1.y = fmaf(w[j], v1.y, a1.y);
        a1.z = fmaf(w[j], v1.z, a1.z);
        a1.w = fmaf(w[j], v1.w, a1.w);
    }

    float* orow = out + (size_t)q * DD + sub * 8;
    *reinterpret_cast<float4*>(orow)     = a0;
    *reinterpret_cast<float4*>(orow + 4) = a1;
}

extern "C" void kernel_launch(void* const* d_in, const int* in_sizes, int n_in,
                              void* d_out, int out_size)
{
    const float* x   = (const float*)d_in[0];   // [B,1]
    const float* ev  = (const float*)d_in[1];   // [T,1]
    const float* tk  = (const float*)d_in[2];   // [T,1]
    const float* vec = (const float*)d_in[3];   // [T,D]
    // d_in[4] = idx_table, compile-time constant window here
    float* out = (float*)d_out;                 // [B,D]

    const int total_threads = BQ * LANES;
    const int blocks = total_threads / BLOCK_THREADS;
    hwnet_kernel<<<blocks, BLOCK_THREADS>>>(x, ev, tk, vec, out);
}

// round 4
// speedup vs baseline: 1.1404x; 1.1404x over previous
#include <cuda_runtime.h>
#include <cuda_bf16.h>
#include <math.h>

// Fixed shapes for HWnet_base_56667798503819
#define BQ 131072   // queries
#define TT 2048     // table size
#define DD 64       // feature dim
#define EE 4        // edge size
#define WW (2*EE+1) // window = 9

// 8 lanes per query; each lane owns 8 floats of D=64 (two float4).
#define LANES 8
#define BLOCK_THREADS 256

__global__ __launch_bounds__(BLOCK_THREADS)
void hwnet_kernel(const float* __restrict__ x,
                  const float* __restrict__ ev,
                  const float* __restrict__ tk,
                  const float* __restrict__ vec,
                  float* __restrict__ out)
{
    const int gtid = blockIdx.x * BLOCK_THREADS + threadIdx.x;
    const int q    = gtid >> 3;      // query index
    const int sub  = gtid & 7;       // 8-float slice within D=64

    const float xv = __ldg(&x[q]);

    // ---- analytic anchor guess (table is a sorted near-linear grid) ----
    const float e0 = __ldg(&ev[0]);
    const float eN = __ldg(&ev[TT - 1]);
    const float invstep = (float)(TT - 1) / (eN - e0);
    int g = __float2int_rn((xv - e0) * invstep);
    g = min(max(g, 0), TT - 1);

    // Every ev value this query needs (fixup candidates g-2..g+2 and the
    // final 9-wide window, which lies in [g-6, g+6]) fits inside a single
    // 16-float aligned span starting at ga.
    int ga = (g - 6) & ~3;
    ga = min(max(ga, 0), TT - 16);

    float v[16];
    {
        const float4* ev4 = reinterpret_cast<const float4*>(ev + ga);
        float4 a = ev4[0], b = ev4[1], c = ev4[2], d4 = ev4[3];
        v[0]=a.x; v[1]=a.y; v[2]=a.z; v[3]=a.w;
        v[4]=b.x; v[5]=b.y; v[6]=b.z; v[7]=b.w;
        v[8]=c.x; v[9]=c.y; v[10]=c.z; v[11]=c.w;
        v[12]=d4.x; v[13]=d4.y; v[14]=d4.z; v[15]=d4.w;
    }

    // ---- exact argmin fixup from registers ----
    // Candidate set = indices within [g-2, g+2] (automatically inside table
    // bounds). Ascending scan + strict '<' == jnp.argmin first-min tie-break.
    int idx = g;
    float best = INFINITY;
    #pragma unroll
    for (int p = 0; p < 16; ++p) {
        const int gi = ga + p;
        const bool valid = (gi >= g - 2) && (gi <= g + 2);
        const float d = fabsf(xv - v[p]);
        if (valid && d < best) { best = d; idx = gi; }
    }

    const float tcare = __ldg(&tk[idx]);       // takecare at UNCLIPPED idx
    const int idx_c = min(max(idx, EE), TT - 1 - EE);
    const int base  = idx_c - EE;
    const int t     = base - ga;               // window start within v[], 0..7

    // ---- extract the 9 window ev values (uniform switch per query group) ----
    float e[WW];
    switch (t) {
    #define CASE(T_) case T_: { _Pragma("unroll") \
        for (int j = 0; j < WW; ++j) e[j] = v[T_ + j]; } break;
    CASE(0) CASE(1) CASE(2) CASE(3) CASE(4) CASE(5) CASE(6) CASE(7)
    #undef CASE
    }

    // ---- window logits + softmax ----
    float w[WW];
    float m = -INFINITY;
    #pragma unroll
    for (int j = 0; j < WW; ++j) {
        float d = xv - e[j];
        w[j] = -(d * d) * tcare;
        m = fmaxf(m, w[j]);
    }
    float s = 0.f;
    #pragma unroll
    for (int j = 0; j < WW; ++j) {
        w[j] = __expf(w[j] - m);
        s += w[j];
    }
    const float inv = 1.0f / s;
    #pragma unroll
    for (int j = 0; j < WW; ++j) w[j] *= inv;

    // ---- gather 9 rows, 8 floats per lane (2 x float4, coalesced 256B/row) ----
    const float* vrow = vec + (size_t)base * DD + sub * 8;
    float4 a0 = make_float4(0.f, 0.f, 0.f, 0.f);
    float4 a1 = make_float4(0.f, 0.f, 0.f, 0.f);
    #pragma unroll
    for (int j = 0; j < WW; ++j) {
        const float4 v0 = *reinterpret_cast<const float4*>(vrow + (size_t)j * DD);
        const float4 v1 = *reinterpret_cast<const float4*>(vrow + (size_t)j * DD + 4);
        a0.x = fmaf(w[j], v0.x, a0.x);
        a0.y = fmaf(w[j], v0.y, a0.y);
        a0.z = fmaf(w[j], v0.z, a0.z);
        a0.w = fmaf(w[j], v0.w, a0.w);
        a1.x = fmaf(w[j], v1.x, a1.x);
        a1.y = fmaf(w[j], v1.y, a1.y);
        a1.z = fmaf(w[j], v1.z, a1.z);
        a1.w = fmaf(w[j], v1.w, a1.w);
    }

    float* orow = out + (size_t)q * DD + sub * 8;
    *reinterpret_cast<float4*>(orow)     = a0;
    *reinterpret_cast<float4*>(orow + 4) = a1;
}

extern "C" void kernel_launch(void* const* d_in, const int* in_sizes, int n_in,
                              void* d_out, int out_size)
{
    const float* x   = (const float*)d_in[0];   // [B,1]
    const float* ev  = (const float*)d_in[1];   // [T,1]
    const float* tk  = (const float*)d_in[2];   // [T,1]
    const float* vec = (const float*)d_in[3];   // [T,D]
    // d_in[4] = idx_table, compile-time constant window here
    float* out = (float*)d_out;                 // [B,D]

    const int total_threads = BQ * LANES;
    const int blocks = total_threads / BLOCK_THREADS;
    hwnet_kernel<<<blocks, BLOCK_THREADS>>>(x, ev, tk, vec, out);
}

// round 5
// speedup vs baseline: 1.2560x; 1.1014x over previous
#include <cuda_runtime.h>
#include <cuda_bf16.h>
#include <math.h>

// Fixed shapes for HWnet_base_56667798503819
#define BQ 131072   // queries
#define TT 2048     // table size
#define DD 64       // feature dim
#define EE 4        // edge size
#define WW (2*EE+1) // window = 9

// 8 lanes per query. Each lane owns TWO float4s at offsets sub*4 and 32+sub*4,
// so that EACH LDG.128 instruction covers one contiguous 128B line per query
// (4 lines per warp = the L1 wavefront floor), instead of striding across both
// lines of the row.
#define LANES 8
#define BLOCK_THREADS 256

__global__ __launch_bounds__(BLOCK_THREADS)
void hwnet_kernel(const float* __restrict__ x,
                  const float* __restrict__ ev,
                  const float* __restrict__ tk,
                  const float* __restrict__ vec,
                  float* __restrict__ out)
{
    const int gtid = blockIdx.x * BLOCK_THREADS + threadIdx.x;
    const int q    = gtid >> 3;      // query index
    const int sub  = gtid & 7;       // lane within query

    const float xv = __ldg(&x[q]);

    // ---- analytic anchor guess (table is a sorted near-linear grid) ----
    const float e0 = __ldg(&ev[0]);
    const float eN = __ldg(&ev[TT - 1]);
    const float invstep = (float)(TT - 1) / (eN - e0);
    int g = __float2int_rn((xv - e0) * invstep);
    g = min(max(g, 0), TT - 1);

    // Every ev value this query needs (fixup candidates g-2..g+2 and the
    // final 9-wide window in [g-6, g+6]) fits in a 16-float aligned span.
    int ga = (g - 6) & ~3;
    ga = min(max(ga, 0), TT - 16);

    float v[16];
    {
        const float4* ev4 = reinterpret_cast<const float4*>(ev + ga);
        float4 a = ev4[0], b = ev4[1], c = ev4[2], d4 = ev4[3];
        v[0]=a.x; v[1]=a.y; v[2]=a.z; v[3]=a.w;
        v[4]=b.x; v[5]=b.y; v[6]=b.z; v[7]=b.w;
        v[8]=c.x; v[9]=c.y; v[10]=c.z; v[11]=c.w;
        v[12]=d4.x; v[13]=d4.y; v[14]=d4.z; v[15]=d4.w;
    }

    // ---- exact argmin fixup from registers ----
    // Candidates = indices in [g-2, g+2]; ascending scan + strict '<'
    // reproduces jnp.argmin first-min tie-break exactly.
    int idx = g;
    float best = INFINITY;
    #pragma unroll
    for (int p = 0; p < 16; ++p) {
        const int gi = ga + p;
        const bool valid = (gi >= g - 2) && (gi <= g + 2);
        const float d = fabsf(xv - v[p]);
        if (valid && d < best) { best = d; idx = gi; }
    }

    const float tcare = __ldg(&tk[idx]);       // takecare at UNCLIPPED idx
    const int idx_c = min(max(idx, EE), TT - 1 - EE);
    const int base  = idx_c - EE;
    const int t     = base - ga;               // window start within v[], 0..7

    // ---- extract 9 window ev values from registers (uniform per query) ----
    float e[WW];
    switch (t) {
    #define CASE(T_) case T_: { _Pragma("unroll") \
        for (int j = 0; j < WW; ++j) e[j] = v[T_ + j]; } break;
    CASE(0) CASE(1) CASE(2) CASE(3) CASE(4) CASE(5) CASE(6) CASE(7)
    #undef CASE
    }

    // ---- window logits + softmax ----
    float w[WW];
    float m = -INFINITY;
    #pragma unroll
    for (int j = 0; j < WW; ++j) {
        float d = xv - e[j];
        w[j] = -(d * d) * tcare;
        m = fmaxf(m, w[j]);
    }
    float s = 0.f;
    #pragma unroll
    for (int j = 0; j < WW; ++j) {
        w[j] = __expf(w[j] - m);
        s += w[j];
    }
    const float inv = 1.0f / s;
    #pragma unroll
    for (int j = 0; j < WW; ++j) w[j] *= inv;

    // ---- gather 9 rows; per instruction each query reads one 128B line ----
    const float* vbase = vec + (size_t)base * DD + sub * 4;
    float4 a0 = make_float4(0.f, 0.f, 0.f, 0.f);   // floats [sub*4, sub*4+4)
    float4 a1 = make_float4(0.f, 0.f, 0.f, 0.f);   // floats [32+sub*4, ...)
    #pragma unroll
    for (int j = 0; j < WW; ++j) {
        const float4 v0 = *reinterpret_cast<const float4*>(vbase + (size_t)j * DD);
        const float4 v1 = *reinterpret_cast<const float4*>(vbase + (size_t)j * DD + 32);
        a0.x = fmaf(w[j], v0.x, a0.x);
        a0.y = fmaf(w[j], v0.y, a0.y);
        a0.z = fmaf(w[j], v0.z, a0.z);
        a0.w = fmaf(w[j], v0.w, a0.w);
        a1.x = fmaf(w[j], v1.x, a1.x);
        a1.y = fmaf(w[j], v1.y, a1.y);
        a1.z = fmaf(w[j], v1.z, a1.z);
        a1.w = fmaf(w[j], v1.w, a1.w);
    }

    float* obase = out + (size_t)q * DD + sub * 4;
    *reinterpret_cast<float4*>(obase)      = a0;
    *reinterpret_cast<float4*>(obase + 32) = a1;
}

extern "C" void kernel_launch(void* const* d_in, const int* in_sizes, int n_in,
                              void* d_out, int out_size)
{
    const float* x   = (const float*)d_in[0];   // [B,1]
    const float* ev  = (const float*)d_in[1];   // [T,1]
    const float* tk  = (const float*)d_in[2];   // [T,1]
    const float* vec = (const float*)d_in[3];   // [T,D]
    // d_in[4] = idx_table, compile-time constant window here
    float* out = (float*)d_out;                 // [B,D]

    const int total_threads = BQ * LANES;
    const int blocks = total_threads / BLOCK_THREADS;
    hwnet_kernel<<<blocks, BLOCK_THREADS>>>(x, ev, tk, vec, out);
}